// round 1
// baseline (speedup 1.0000x reference)
#include <cuda_runtime.h>
#include <math.h>

#define HID   128
#define MAXN  50000
#define MAXE  800000
#define RNUM  8
#define HEADS 4
#define FFDIM 512

// ---------------- scratch (device globals: allocation-free rule) ----------------
__device__ float    g_h1  [(size_t)MAXN*HID];          // LN1(x)
__device__ float    g_xr  [(size_t)RNUM*MAXN*HID];     // relation-wise projections
__device__ float    g_asrc[(size_t)RNUM*MAXN*HEADS];   // per (r,n,h) src dots
__device__ float    g_adst[(size_t)RNUM*MAXN*HEADS];   // per (r,n,h) dst dots
__device__ float    g_alpha[(size_t)MAXE*HEADS];       // logits -> exp values
__device__ unsigned g_amax[(size_t)MAXN*HEADS];        // segment max (encoded)
__device__ float    g_den [(size_t)MAXN*HEADS];        // segment sum
__device__ float    g_outc[(size_t)MAXN*HID];          // conv output accumulator
__device__ float    g_h2  [(size_t)MAXN*HID];          // LN2 output
__device__ float    g_t   [(size_t)MAXN*FFDIM];        // FFN hidden
__device__ float    g_er  [RNUM*HEADS];                // edge-emb dot att_edge

// ---------------- helpers ----------------
__device__ __forceinline__ unsigned fenc(float f) {
    unsigned u = __float_as_uint(f);
    return (u & 0x80000000u) ? ~u : (u | 0x80000000u);
}
__device__ __forceinline__ float fdec(unsigned u) {
    return (u & 0x80000000u) ? __uint_as_float(u & 0x7fffffffu)
                             : __uint_as_float(~u);
}
__device__ __forceinline__ float geluf(float v) {
    return 0.5f * v * (1.0f + erff(v * 0.7071067811865475f));
}
__device__ __forceinline__ float eluf(float v) {
    return v > 0.0f ? v : expm1f(v);
}
__device__ __forceinline__ float lreluf(float v) {
    return v > 0.0f ? v : 0.2f * v;
}

// ---------------- init ----------------
__global__ void init_kernel(int Nn) {
    int i = blockIdx.x * blockDim.x + threadIdx.x;
    if (i < Nn * HEADS) { g_amax[i] = 0u; g_den[i] = 0.0f; }
}

// e_r[r,h] = sum_d edge_emb_table[r, h*32+d] * att_edge[h*32+d]
__global__ void er_kernel(const float* __restrict__ emb,
                          const float* __restrict__ att_edge) {
    int t = threadIdx.x;                 // 32 threads: r=t>>2, h=t&3
    int r = t >> 2, h = t & 3;
    float s = 0.0f;
    #pragma unroll
    for (int d = 0; d < 32; d++)
        s += emb[r * HID + h * 32 + d] * att_edge[h * 32 + d];
    g_er[r * HEADS + h] = s;
}

// ---------------- layernorm (warp per row, 128 cols) ----------------
__global__ void ln_kernel(const float* __restrict__ x,
                          const float* __restrict__ w,
                          const float* __restrict__ b,
                          float* __restrict__ out, int Nn) {
    int gw = (blockIdx.x * blockDim.x + threadIdx.x) >> 5;
    int lane = threadIdx.x & 31;
    if (gw >= Nn) return;
    const float4 v = *(const float4*)(x + (size_t)gw * HID + lane * 4);
    float s = v.x + v.y + v.z + v.w;
    float q = v.x * v.x + v.y * v.y + v.z * v.z + v.w * v.w;
    #pragma unroll
    for (int o = 16; o; o >>= 1) {
        s += __shfl_xor_sync(0xffffffffu, s, o);
        q += __shfl_xor_sync(0xffffffffu, q, o);
    }
    float mu = s * (1.0f / HID);
    float var = q * (1.0f / HID) - mu * mu;
    float rstd = rsqrtf(var + 1e-5f);
    float4 wv = *(const float4*)(w + lane * 4);
    float4 bv = *(const float4*)(b + lane * 4);
    float4 o4;
    o4.x = (v.x - mu) * rstd * wv.x + bv.x;
    o4.y = (v.y - mu) * rstd * wv.y + bv.y;
    o4.z = (v.z - mu) * rstd * wv.z + bv.z;
    o4.w = (v.w - mu) * rstd * wv.w + bv.w;
    *(float4*)(out + (size_t)gw * HID + lane * 4) = o4;
}

// ---------------- generic fp32 GEMM: C = act(A@B + bias) (+resid) ----------------
// BM=64, BN=128, BK=32, 256 threads, each thread 8x4 microtile.
#define BM 64
#define BN 128
#define BKK 32
__global__ __launch_bounds__(256)
void gemm_kernel(const float* __restrict__ A, const float* __restrict__ B,
                 float* __restrict__ C, const float* __restrict__ bias,
                 const float* __restrict__ resid,
                 int M, int K, int ncols, int act,
                 long strideB, long strideC) {
    __shared__ float As[BM][BKK];
    __shared__ float Bs[BKK][BN];
    const float* Bb = B + (long)blockIdx.z * strideB;
    float* Cb = C + (long)blockIdx.z * strideC;
    int m0 = blockIdx.x * BM;
    int n0 = blockIdx.y * BN;
    int tid = threadIdx.x;
    int tx = tid & 31, ty = tid >> 5;
    float acc[8][4];
    #pragma unroll
    for (int i = 0; i < 8; i++)
        #pragma unroll
        for (int j = 0; j < 4; j++) acc[i][j] = 0.0f;

    for (int k0 = 0; k0 < K; k0 += BKK) {
        // A tile: 64x32 floats = 512 float4 -> 2 per thread
        #pragma unroll
        for (int l = 0; l < 2; l++) {
            int idx = tid + l * 256;
            int row = idx >> 3, c4 = idx & 7;
            float4 v = make_float4(0.f, 0.f, 0.f, 0.f);
            if (m0 + row < M)
                v = *(const float4*)(A + (long)(m0 + row) * K + k0 + c4 * 4);
            *(float4*)(&As[row][c4 * 4]) = v;
        }
        // B tile: 32x128 = 1024 float4 -> 4 per thread
        #pragma unroll
        for (int l = 0; l < 4; l++) {
            int idx = tid + l * 256;
            int row = idx >> 5, c4 = idx & 31;
            float4 v = *(const float4*)(Bb + (long)(k0 + row) * ncols + n0 + c4 * 4);
            *(float4*)(&Bs[row][c4 * 4]) = v;
        }
        __syncthreads();
        #pragma unroll
        for (int k = 0; k < BKK; k++) {
            float4 b4 = *(const float4*)(&Bs[k][tx * 4]);
            #pragma unroll
            for (int i = 0; i < 8; i++) {
                float a = As[ty * 8 + i][k];
                acc[i][0] += a * b4.x;
                acc[i][1] += a * b4.y;
                acc[i][2] += a * b4.z;
                acc[i][3] += a * b4.w;
            }
        }
        __syncthreads();
    }
    int col = n0 + tx * 4;
    float4 bv = make_float4(0.f, 0.f, 0.f, 0.f);
    if (bias) bv = *(const float4*)(bias + col);
    #pragma unroll
    for (int i = 0; i < 8; i++) {
        int row = m0 + ty * 8 + i;
        if (row >= M) continue;
        float4 v = make_float4(acc[i][0] + bv.x, acc[i][1] + bv.y,
                               acc[i][2] + bv.z, acc[i][3] + bv.w);
        if (act == 1) { v.x = geluf(v.x); v.y = geluf(v.y); v.z = geluf(v.z); v.w = geluf(v.w); }
        if (resid) {
            float4 r = *(const float4*)(resid + (long)row * ncols + col);
            v.x += r.x; v.y += r.y; v.z += r.z; v.w += r.w;
        }
        *(float4*)(Cb + (long)row * ncols + col) = v;
    }
}

// ---------------- per (r,n) attention dot products (warp per (r,n)) ----------------
__global__ void attn_dots_kernel(const float* __restrict__ att_src,
                                 const float* __restrict__ att_dst,
                                 int Nn, int R) {
    long gw = ((long)blockIdx.x * blockDim.x + threadIdx.x) >> 5;
    int lane = threadIdx.x & 31;
    if (gw >= (long)R * Nn) return;
    int r = (int)(gw / Nn), n = (int)(gw % Nn);
    float4 xv = *(const float4*)(g_xr + ((long)r * Nn + n) * HID + lane * 4);
    float4 s4 = *(const float4*)(att_src + lane * 4);
    float4 d4 = *(const float4*)(att_dst + lane * 4);
    float ps = xv.x * s4.x + xv.y * s4.y + xv.z * s4.z + xv.w * s4.w;
    float pd = xv.x * d4.x + xv.y * d4.y + xv.z * d4.z + xv.w * d4.w;
    #pragma unroll
    for (int o = 4; o; o >>= 1) {
        ps += __shfl_xor_sync(0xffffffffu, ps, o);
        pd += __shfl_xor_sync(0xffffffffu, pd, o);
    }
    if ((lane & 7) == 0) {
        int h = lane >> 3;
        g_asrc[((long)r * Nn + n) * HEADS + h] = ps;
        g_adst[((long)r * Nn + n) * HEADS + h] = pd;
    }
}

// ---------------- edge pass 1: logits + segment max ----------------
__global__ void edge_pass1(const int* __restrict__ ei, const int* __restrict__ et,
                           int E, int Nn) {
    int e = blockIdx.x * blockDim.x + threadIdx.x;
    if (e >= E) return;
    int r = et[e];
    int s = ei[e];
    int d = ei[E + e];
    float4 as = *(const float4*)(g_asrc + ((long)r * Nn + s) * HEADS);
    float4 ad = *(const float4*)(g_adst + ((long)r * Nn + d) * HEADS);
    float4 er = *(const float4*)(g_er + r * HEADS);
    float a0 = lreluf(as.x + ad.x + er.x);
    float a1 = lreluf(as.y + ad.y + er.y);
    float a2 = lreluf(as.z + ad.z + er.z);
    float a3 = lreluf(as.w + ad.w + er.w);
    *(float4*)(g_alpha + (long)e * HEADS) = make_float4(a0, a1, a2, a3);
    unsigned* am = g_amax + (long)d * HEADS;
    atomicMax(am + 0, fenc(a0));
    atomicMax(am + 1, fenc(a1));
    atomicMax(am + 2, fenc(a2));
    atomicMax(am + 3, fenc(a3));
}

// ---------------- edge pass 2: exp + segment sum ----------------
__global__ void edge_pass2(const int* __restrict__ ei, int E) {
    int e = blockIdx.x * blockDim.x + threadIdx.x;
    if (e >= E) return;
    int d = ei[E + e];
    float4 a = *(const float4*)(g_alpha + (long)e * HEADS);
    const unsigned* am = g_amax + (long)d * HEADS;
    float e0 = expf(a.x - fdec(am[0]));
    float e1 = expf(a.y - fdec(am[1]));
    float e2 = expf(a.z - fdec(am[2]));
    float e3 = expf(a.w - fdec(am[3]));
    *(float4*)(g_alpha + (long)e * HEADS) = make_float4(e0, e1, e2, e3);
    float* dn = g_den + (long)d * HEADS;
    atomicAdd(dn + 0, e0);
    atomicAdd(dn + 1, e1);
    atomicAdd(dn + 2, e2);
    atomicAdd(dn + 3, e3);
}

// ---------------- edge pass 3: weighted message scatter (warp per edge) ----------------
__global__ void edge_pass3(const int* __restrict__ ei, const int* __restrict__ et,
                           int E, int Nn) {
    long gw = ((long)blockIdx.x * blockDim.x + threadIdx.x) >> 5;
    int lane = threadIdx.x & 31;
    if (gw >= E) return;
    int r = et[gw];
    int s = ei[gw];
    int d = ei[E + gw];
    int h = lane >> 3;
    float ex = g_alpha[gw * HEADS + h];
    float dn = g_den[(long)d * HEADS + h];
    float w = ex / (dn + 1e-16f);
    float4 xs = *(const float4*)(g_xr + ((long)r * Nn + s) * HID + lane * 4);
    float* o = g_outc + (long)d * HID + lane * 4;
    atomicAdd(o + 0, xs.x * w);
    atomicAdd(o + 1, xs.y * w);
    atomicAdd(o + 2, xs.z * w);
    atomicAdd(o + 3, xs.w * w);
}

// ---------------- post: elu + residual + LN2 (warp per row) ----------------
__global__ void post_kernel(const float* __restrict__ x,
                            const float* __restrict__ w,
                            const float* __restrict__ b,
                            float* __restrict__ x1out, int Nn) {
    int gw = (blockIdx.x * blockDim.x + threadIdx.x) >> 5;
    int lane = threadIdx.x & 31;
    if (gw >= Nn) return;
    float4 oc = *(const float4*)(g_outc + (size_t)gw * HID + lane * 4);
    oc.x = eluf(oc.x); oc.y = eluf(oc.y); oc.z = eluf(oc.z); oc.w = eluf(oc.w);
    float4 xv = *(const float4*)(x + (size_t)gw * HID + lane * 4);
    float4 x1 = make_float4(xv.x + oc.x, xv.y + oc.y, xv.z + oc.z, xv.w + oc.w);
    *(float4*)(x1out + (size_t)gw * HID + lane * 4) = x1;
    float s = x1.x + x1.y + x1.z + x1.w;
    float q = x1.x * x1.x + x1.y * x1.y + x1.z * x1.z + x1.w * x1.w;
    #pragma unroll
    for (int o = 16; o; o >>= 1) {
        s += __shfl_xor_sync(0xffffffffu, s, o);
        q += __shfl_xor_sync(0xffffffffu, q, o);
    }
    float mu = s * (1.0f / HID);
    float var = q * (1.0f / HID) - mu * mu;
    float rstd = rsqrtf(var + 1e-5f);
    float4 wv = *(const float4*)(w + lane * 4);
    float4 bv = *(const float4*)(b + lane * 4);
    float4 o4;
    o4.x = (x1.x - mu) * rstd * wv.x + bv.x;
    o4.y = (x1.y - mu) * rstd * wv.y + bv.y;
    o4.z = (x1.z - mu) * rstd * wv.z + bv.z;
    o4.w = (x1.w - mu) * rstd * wv.w + bv.w;
    *(float4*)(g_h2 + (size_t)gw * HID + lane * 4) = o4;
}

// ---------------- launch ----------------
extern "C" void kernel_launch(void* const* d_in, const int* in_sizes, int n_in,
                              void* d_out, int out_size) {
    const float* x          = (const float*)d_in[0];
    const float* weight     = (const float*)d_in[1];
    const float* root_w     = (const float*)d_in[2];
    const float* edge_emb   = (const float*)d_in[3];
    const float* att_src    = (const float*)d_in[4];
    const float* att_dst    = (const float*)d_in[5];
    const float* att_edge   = (const float*)d_in[6];
    const float* bias       = (const float*)d_in[7];
    const float* n1w        = (const float*)d_in[8];
    const float* n1b        = (const float*)d_in[9];
    const float* n2w        = (const float*)d_in[10];
    const float* n2b        = (const float*)d_in[11];
    const float* ffn_w1     = (const float*)d_in[12];
    const float* ffn_b1     = (const float*)d_in[13];
    const float* ffn_w2     = (const float*)d_in[14];
    const float* ffn_b2     = (const float*)d_in[15];
    const int*   edge_index = (const int*)d_in[16];
    const int*   edge_type  = (const int*)d_in[17];
    float* out = (float*)d_out;

    int N = in_sizes[0] / HID;
    int E = in_sizes[17];
    int R = in_sizes[1] / (HID * HID);

    float *p_h1, *p_xr, *p_outc, *p_h2, *p_t;
    cudaGetSymbolAddress((void**)&p_h1,   g_h1);
    cudaGetSymbolAddress((void**)&p_xr,   g_xr);
    cudaGetSymbolAddress((void**)&p_outc, g_outc);
    cudaGetSymbolAddress((void**)&p_h2,   g_h2);
    cudaGetSymbolAddress((void**)&p_t,    g_t);

    int rowBlocks = (N + 7) / 8;                 // warp-per-row kernels, 256 thr
    int mTiles    = (N + BM - 1) / BM;

    init_kernel<<<(N * HEADS + 255) / 256, 256>>>(N);
    er_kernel<<<1, 32>>>(edge_emb, att_edge);
    ln_kernel<<<rowBlocks, 256>>>(x, n1w, n1b, p_h1, N);

    // relation-wise projection: x_r[r] = h1 @ weight[r]
    gemm_kernel<<<dim3(mTiles, 1, R), 256>>>(p_h1, weight, p_xr, nullptr, nullptr,
                                             N, HID, HID, 0,
                                             (long)HID * HID, (long)N * HID);
    attn_dots_kernel<<<(int)(((long)R * N + 7) / 8), 256>>>(att_src, att_dst, N, R);
    edge_pass1<<<(E + 255) / 256, 256>>>(edge_index, edge_type, E, N);
    edge_pass2<<<(E + 255) / 256, 256>>>(edge_index, E);

    // root term first (writes g_outc), then messages atomically accumulate on top
    gemm_kernel<<<dim3(mTiles, 1, 1), 256>>>(p_h1, root_w, p_outc, bias, nullptr,
                                             N, HID, HID, 0, 0, 0);
    edge_pass3<<<(E + 7) / 8, 256>>>(edge_index, edge_type, E, N);

    // elu + residual (-> d_out as x1) + LN2 (-> g_h2)
    post_kernel<<<rowBlocks, 256>>>(x, n2w, n2b, out, N);

    // FFN
    gemm_kernel<<<dim3(mTiles, 4, 1), 256>>>(p_h2, ffn_w1, p_t, ffn_b1, nullptr,
                                             N, HID, FFDIM, 1, 0, 0);
    gemm_kernel<<<dim3(mTiles, 1, 1), 256>>>(p_t, ffn_w2, out, ffn_b2, out,
                                             N, FFDIM, HID, 0, 0, 0);
}

// round 2
// speedup vs baseline: 1.7080x; 1.7080x over previous
#include <cuda_runtime.h>
#include <math.h>

#define HID   128
#define MAXN  50000
#define MAXE  800000
#define RNUM  8
#define HEADS 4
#define FFDIM 512

// ---------------- scratch (device globals: allocation-free rule) ----------------
__device__ float    g_h1  [(size_t)MAXN*HID];
__device__ float    g_xr  [(size_t)RNUM*MAXN*HID];
__device__ float    g_asrc[(size_t)RNUM*MAXN*HEADS];
__device__ float    g_adst[(size_t)RNUM*MAXN*HEADS];
__device__ float    g_alpha[(size_t)MAXE*HEADS];
__device__ unsigned g_amax[(size_t)MAXN*HEADS];
__device__ float    g_den [(size_t)MAXN*HEADS];
__device__ float    g_outc[(size_t)MAXN*HID];
__device__ float    g_h2  [(size_t)MAXN*HID];
__device__ float    g_t   [(size_t)MAXN*FFDIM];
__device__ float    g_er  [RNUM*HEADS];

// ---------------- helpers ----------------
__device__ __forceinline__ unsigned fenc(float f) {
    unsigned u = __float_as_uint(f);
    return (u & 0x80000000u) ? ~u : (u | 0x80000000u);
}
__device__ __forceinline__ float fdec(unsigned u) {
    return (u & 0x80000000u) ? __uint_as_float(u & 0x7fffffffu)
                             : __uint_as_float(~u);
}
__device__ __forceinline__ float geluf(float v) {
    return 0.5f * v * (1.0f + erff(v * 0.7071067811865475f));
}
__device__ __forceinline__ float eluf(float v) {
    return v > 0.0f ? v : expm1f(v);
}
__device__ __forceinline__ float lreluf(float v) {
    return v > 0.0f ? v : 0.2f * v;
}
__device__ __forceinline__ float tf32r(float v) {
    float o;
    asm("cvt.rna.tf32.f32 %0, %1;" : "=f"(o) : "f"(v));
    return o;
}

// ---------------- init ----------------
__global__ void init_kernel(int Nn) {
    int i = blockIdx.x * blockDim.x + threadIdx.x;
    if (i < Nn * HEADS) { g_amax[i] = 0u; g_den[i] = 0.0f; }
}

__global__ void er_kernel(const float* __restrict__ emb,
                          const float* __restrict__ att_edge) {
    int t = threadIdx.x;
    int r = t >> 2, h = t & 3;
    float s = 0.0f;
    #pragma unroll
    for (int d = 0; d < 32; d++)
        s += emb[r * HID + h * 32 + d] * att_edge[h * 32 + d];
    g_er[r * HEADS + h] = s;
}

// ---------------- layernorm (warp per row, 128 cols) ----------------
__global__ void ln_kernel(const float* __restrict__ x,
                          const float* __restrict__ w,
                          const float* __restrict__ b,
                          float* __restrict__ out, int Nn) {
    int gw = (blockIdx.x * blockDim.x + threadIdx.x) >> 5;
    int lane = threadIdx.x & 31;
    if (gw >= Nn) return;
    const float4 v = *(const float4*)(x + (size_t)gw * HID + lane * 4);
    float s = v.x + v.y + v.z + v.w;
    float q = v.x * v.x + v.y * v.y + v.z * v.z + v.w * v.w;
    #pragma unroll
    for (int o = 16; o; o >>= 1) {
        s += __shfl_xor_sync(0xffffffffu, s, o);
        q += __shfl_xor_sync(0xffffffffu, q, o);
    }
    float mu = s * (1.0f / HID);
    float var = q * (1.0f / HID) - mu * mu;
    float rstd = rsqrtf(var + 1e-5f);
    float4 wv = *(const float4*)(w + lane * 4);
    float4 bv = *(const float4*)(b + lane * 4);
    float4 o4;
    o4.x = (v.x - mu) * rstd * wv.x + bv.x;
    o4.y = (v.y - mu) * rstd * wv.y + bv.y;
    o4.z = (v.z - mu) * rstd * wv.z + bv.z;
    o4.w = (v.w - mu) * rstd * wv.w + bv.w;
    *(float4*)(out + (size_t)gw * HID + lane * 4) = o4;
}

// ---------------- tf32 tensor-core GEMM: C = act(A@B + bias) (+resid) -----------
// BM=128, BN=128, BK=16. 256 threads = 8 warps (2x4). Warp tile 64x32.
// mma.sync.aligned.m16n8k8.row.col.f32.tf32.tf32.f32
#define APAD 20   // 16 + 4  -> conflict-free A frag loads
#define BPAD 136  // 128 + 8 -> conflict-free B frag loads
__global__ __launch_bounds__(256)
void gemm_tf32(const float* __restrict__ A, const float* __restrict__ B,
               float* __restrict__ C, const float* __restrict__ bias,
               const float* __restrict__ resid,
               int M, int K, int ncols, int act,
               long strideB, long strideC) {
    __shared__ float As[2][128][APAD];
    __shared__ float Bs[2][16][BPAD];

    const float* Bb = B + (long)blockIdx.z * strideB;
    float* Cb = C + (long)blockIdx.z * strideC;
    const int m0 = blockIdx.x * 128;
    const int n0 = blockIdx.y * 128;
    const int tid = threadIdx.x;
    const int wid = tid >> 5, lane = tid & 31;
    const int wm = wid >> 2, wn = wid & 3;        // 2 x 4 warps
    const int g = lane >> 2, tg = lane & 3;

    float acc[4][4][4];
    #pragma unroll
    for (int i = 0; i < 4; i++)
        #pragma unroll
        for (int j = 0; j < 4; j++)
            #pragma unroll
            for (int c = 0; c < 4; c++) acc[i][j][c] = 0.0f;

    // load-index precompute
    const int la_row0 = tid >> 2, la_q = tid & 3;          // A: 2 chunks of 64 rows
    const int lb_c = tid & 31;                             // B: rows tid>>5, +8

    const int nk = K >> 4;

    // ---- fill buffer 0 ----
    {
        #pragma unroll
        for (int l = 0; l < 2; l++) {
            int row = la_row0 + l * 64;
            float4 v = make_float4(0.f,0.f,0.f,0.f);
            if (m0 + row < M)
                v = *(const float4*)(A + (long)(m0 + row) * K + la_q * 4);
            As[0][row][la_q*4+0] = tf32r(v.x);
            As[0][row][la_q*4+1] = tf32r(v.y);
            As[0][row][la_q*4+2] = tf32r(v.z);
            As[0][row][la_q*4+3] = tf32r(v.w);
        }
        #pragma unroll
        for (int l = 0; l < 2; l++) {
            int row = (tid >> 5) + l * 8;
            float4 v = *(const float4*)(Bb + (long)row * ncols + n0 + lb_c * 4);
            Bs[0][row][lb_c*4+0] = tf32r(v.x);
            Bs[0][row][lb_c*4+1] = tf32r(v.y);
            Bs[0][row][lb_c*4+2] = tf32r(v.z);
            Bs[0][row][lb_c*4+3] = tf32r(v.w);
        }
    }
    __syncthreads();

    for (int it = 0; it < nk; it++) {
        int buf = it & 1;
        // prefetch next tile into registers
        float4 ra[2], rb[2];
        bool have_next = (it + 1 < nk);
        if (have_next) {
            int k0 = (it + 1) << 4;
            #pragma unroll
            for (int l = 0; l < 2; l++) {
                int row = la_row0 + l * 64;
                ra[l] = make_float4(0.f,0.f,0.f,0.f);
                if (m0 + row < M)
                    ra[l] = *(const float4*)(A + (long)(m0 + row) * K + k0 + la_q * 4);
            }
            #pragma unroll
            for (int l = 0; l < 2; l++) {
                int row = (tid >> 5) + l * 8;
                rb[l] = *(const float4*)(Bb + (long)(k0 + row) * ncols + n0 + lb_c * 4);
            }
        }

        // compute on buf
        #pragma unroll
        for (int kk = 0; kk < 16; kk += 8) {
            unsigned af[4][4];
            #pragma unroll
            for (int tm = 0; tm < 4; tm++) {
                int rb_ = wm * 64 + tm * 16;
                af[tm][0] = __float_as_uint(As[buf][rb_ + g     ][kk + tg    ]);
                af[tm][1] = __float_as_uint(As[buf][rb_ + g + 8 ][kk + tg    ]);
                af[tm][2] = __float_as_uint(As[buf][rb_ + g     ][kk + tg + 4]);
                af[tm][3] = __float_as_uint(As[buf][rb_ + g + 8 ][kk + tg + 4]);
            }
            unsigned bf0[4], bf1[4];
            #pragma unroll
            for (int tn = 0; tn < 4; tn++) {
                int cb = wn * 32 + tn * 8;
                bf0[tn] = __float_as_uint(Bs[buf][kk + tg    ][cb + g]);
                bf1[tn] = __float_as_uint(Bs[buf][kk + tg + 4][cb + g]);
            }
            #pragma unroll
            for (int tm = 0; tm < 4; tm++)
                #pragma unroll
                for (int tn = 0; tn < 4; tn++) {
                    asm volatile(
                        "mma.sync.aligned.m16n8k8.row.col.f32.tf32.tf32.f32 "
                        "{%0,%1,%2,%3}, {%4,%5,%6,%7}, {%8,%9}, {%0,%1,%2,%3};"
                        : "+f"(acc[tm][tn][0]), "+f"(acc[tm][tn][1]),
                          "+f"(acc[tm][tn][2]), "+f"(acc[tm][tn][3])
                        : "r"(af[tm][0]), "r"(af[tm][1]), "r"(af[tm][2]), "r"(af[tm][3]),
                          "r"(bf0[tn]), "r"(bf1[tn]));
                }
        }

        if (have_next) {
            int nb = 1 - buf;
            #pragma unroll
            for (int l = 0; l < 2; l++) {
                int row = la_row0 + l * 64;
                As[nb][row][la_q*4+0] = tf32r(ra[l].x);
                As[nb][row][la_q*4+1] = tf32r(ra[l].y);
                As[nb][row][la_q*4+2] = tf32r(ra[l].z);
                As[nb][row][la_q*4+3] = tf32r(ra[l].w);
            }
            #pragma unroll
            for (int l = 0; l < 2; l++) {
                int row = (tid >> 5) + l * 8;
                Bs[nb][row][lb_c*4+0] = tf32r(rb[l].x);
                Bs[nb][row][lb_c*4+1] = tf32r(rb[l].y);
                Bs[nb][row][lb_c*4+2] = tf32r(rb[l].z);
                Bs[nb][row][lb_c*4+3] = tf32r(rb[l].w);
            }
        }
        __syncthreads();
    }

    // ---- epilogue ----
    #pragma unroll
    for (int tm = 0; tm < 4; tm++) {
        int r0 = m0 + wm * 64 + tm * 16 + g;
        #pragma unroll
        for (int tn = 0; tn < 4; tn++) {
            int col = n0 + wn * 32 + tn * 8 + 2 * tg;
            float2 bv = make_float2(0.f, 0.f);
            if (bias) bv = *(const float2*)(bias + col);
            #pragma unroll
            for (int half = 0; half < 2; half++) {
                int row = r0 + half * 8;
                if (row >= M) continue;
                float v0 = acc[tm][tn][half*2+0] + bv.x;
                float v1 = acc[tm][tn][half*2+1] + bv.y;
                if (act == 1) { v0 = geluf(v0); v1 = geluf(v1); }
                if (resid) {
                    float2 rr = *(const float2*)(resid + (long)row * ncols + col);
                    v0 += rr.x; v1 += rr.y;
                }
                *(float2*)(Cb + (long)row * ncols + col) = make_float2(v0, v1);
            }
        }
    }
}

// ---------------- per (r,n) attention dot products (warp per (r,n)) -------------
__global__ void attn_dots_kernel(const float* __restrict__ att_src,
                                 const float* __restrict__ att_dst,
                                 int Nn, int R) {
    long gw = ((long)blockIdx.x * blockDim.x + threadIdx.x) >> 5;
    int lane = threadIdx.x & 31;
    if (gw >= (long)R * Nn) return;
    int r = (int)(gw / Nn), n = (int)(gw % Nn);
    float4 xv = *(const float4*)(g_xr + ((long)r * Nn + n) * HID + lane * 4);
    float4 s4 = *(const float4*)(att_src + lane * 4);
    float4 d4 = *(const float4*)(att_dst + lane * 4);
    float ps = xv.x * s4.x + xv.y * s4.y + xv.z * s4.z + xv.w * s4.w;
    float pd = xv.x * d4.x + xv.y * d4.y + xv.z * d4.z + xv.w * d4.w;
    #pragma unroll
    for (int o = 4; o; o >>= 1) {
        ps += __shfl_xor_sync(0xffffffffu, ps, o);
        pd += __shfl_xor_sync(0xffffffffu, pd, o);
    }
    if ((lane & 7) == 0) {
        int h = lane >> 3;
        g_asrc[((long)r * Nn + n) * HEADS + h] = ps;
        g_adst[((long)r * Nn + n) * HEADS + h] = pd;
    }
}

// ---------------- edge pass 1: logits + segment max ----------------
__global__ void edge_pass1(const int* __restrict__ ei, const int* __restrict__ et,
                           int E, int Nn) {
    int e = blockIdx.x * blockDim.x + threadIdx.x;
    if (e >= E) return;
    int r = et[e];
    int s = ei[e];
    int d = ei[E + e];
    float4 as = *(const float4*)(g_asrc + ((long)r * Nn + s) * HEADS);
    float4 ad = *(const float4*)(g_adst + ((long)r * Nn + d) * HEADS);
    float4 er = *(const float4*)(g_er + r * HEADS);
    float a0 = lreluf(as.x + ad.x + er.x);
    float a1 = lreluf(as.y + ad.y + er.y);
    float a2 = lreluf(as.z + ad.z + er.z);
    float a3 = lreluf(as.w + ad.w + er.w);
    *(float4*)(g_alpha + (long)e * HEADS) = make_float4(a0, a1, a2, a3);
    unsigned* am = g_amax + (long)d * HEADS;
    atomicMax(am + 0, fenc(a0));
    atomicMax(am + 1, fenc(a1));
    atomicMax(am + 2, fenc(a2));
    atomicMax(am + 3, fenc(a3));
}

// ---------------- edge pass 2: exp + segment sum ----------------
__global__ void edge_pass2(const int* __restrict__ ei, int E) {
    int e = blockIdx.x * blockDim.x + threadIdx.x;
    if (e >= E) return;
    int d = ei[E + e];
    float4 a = *(const float4*)(g_alpha + (long)e * HEADS);
    const unsigned* am = g_amax + (long)d * HEADS;
    float e0 = expf(a.x - fdec(am[0]));
    float e1 = expf(a.y - fdec(am[1]));
    float e2 = expf(a.z - fdec(am[2]));
    float e3 = expf(a.w - fdec(am[3]));
    *(float4*)(g_alpha + (long)e * HEADS) = make_float4(e0, e1, e2, e3);
    float* dn = g_den + (long)d * HEADS;
    atomicAdd(dn + 0, e0);
    atomicAdd(dn + 1, e1);
    atomicAdd(dn + 2, e2);
    atomicAdd(dn + 3, e3);
}

// ---------------- edge pass 3: weighted message scatter (warp per edge) ---------
__global__ void edge_pass3(const int* __restrict__ ei, const int* __restrict__ et,
                           int E, int Nn) {
    long gw = ((long)blockIdx.x * blockDim.x + threadIdx.x) >> 5;
    int lane = threadIdx.x & 31;
    if (gw >= E) return;
    int r = et[gw];
    int s = ei[gw];
    int d = ei[E + gw];
    int h = lane >> 3;
    float ex = g_alpha[gw * HEADS + h];
    float dn = g_den[(long)d * HEADS + h];
    float w = ex / (dn + 1e-16f);
    float4 xs = *(const float4*)(g_xr + ((long)r * Nn + s) * HID + lane * 4);
    float* o = g_outc + (long)d * HID + lane * 4;
    asm volatile("red.global.add.v4.f32 [%0], {%1,%2,%3,%4};"
                 :: "l"(o), "f"(xs.x * w), "f"(xs.y * w),
                    "f"(xs.z * w), "f"(xs.w * w)
                 : "memory");
}

// ---------------- post: elu + residual + LN2 (warp per row) ----------------
__global__ void post_kernel(const float* __restrict__ x,
                            const float* __restrict__ w,
                            const float* __restrict__ b,
                            float* __restrict__ x1out, int Nn) {
    int gw = (blockIdx.x * blockDim.x + threadIdx.x) >> 5;
    int lane = threadIdx.x & 31;
    if (gw >= Nn) return;
    float4 oc = *(const float4*)(g_outc + (size_t)gw * HID + lane * 4);
    oc.x = eluf(oc.x); oc.y = eluf(oc.y); oc.z = eluf(oc.z); oc.w = eluf(oc.w);
    float4 xv = *(const float4*)(x + (size_t)gw * HID + lane * 4);
    float4 x1 = make_float4(xv.x + oc.x, xv.y + oc.y, xv.z + oc.z, xv.w + oc.w);
    *(float4*)(x1out + (size_t)gw * HID + lane * 4) = x1;
    float s = x1.x + x1.y + x1.z + x1.w;
    float q = x1.x * x1.x + x1.y * x1.y + x1.z * x1.z + x1.w * x1.w;
    #pragma unroll
    for (int o = 16; o; o >>= 1) {
        s += __shfl_xor_sync(0xffffffffu, s, o);
        q += __shfl_xor_sync(0xffffffffu, q, o);
    }
    float mu = s * (1.0f / HID);
    float var = q * (1.0f / HID) - mu * mu;
    float rstd = rsqrtf(var + 1e-5f);
    float4 wv = *(const float4*)(w + lane * 4);
    float4 bv = *(const float4*)(b + lane * 4);
    float4 o4;
    o4.x = (x1.x - mu) * rstd * wv.x + bv.x;
    o4.y = (x1.y - mu) * rstd * wv.y + bv.y;
    o4.z = (x1.z - mu) * rstd * wv.z + bv.z;
    o4.w = (x1.w - mu) * rstd * wv.w + bv.w;
    *(float4*)(g_h2 + (size_t)gw * HID + lane * 4) = o4;
}

// ---------------- launch ----------------
extern "C" void kernel_launch(void* const* d_in, const int* in_sizes, int n_in,
                              void* d_out, int out_size) {
    const float* x          = (const float*)d_in[0];
    const float* weight     = (const float*)d_in[1];
    const float* root_w     = (const float*)d_in[2];
    const float* edge_emb   = (const float*)d_in[3];
    const float* att_src    = (const float*)d_in[4];
    const float* att_dst    = (const float*)d_in[5];
    const float* att_edge   = (const float*)d_in[6];
    const float* bias       = (const float*)d_in[7];
    const float* n1w        = (const float*)d_in[8];
    const float* n1b        = (const float*)d_in[9];
    const float* n2w        = (const float*)d_in[10];
    const float* n2b        = (const float*)d_in[11];
    const float* ffn_w1     = (const float*)d_in[12];
    const float* ffn_b1     = (const float*)d_in[13];
    const float* ffn_w2     = (const float*)d_in[14];
    const float* ffn_b2     = (const float*)d_in[15];
    const int*   edge_index = (const int*)d_in[16];
    const int*   edge_type  = (const int*)d_in[17];
    float* out = (float*)d_out;

    int N = in_sizes[0] / HID;
    int E = in_sizes[17];
    int R = in_sizes[1] / (HID * HID);

    float *p_h1, *p_xr, *p_outc, *p_h2, *p_t;
    cudaGetSymbolAddress((void**)&p_h1,   g_h1);
    cudaGetSymbolAddress((void**)&p_xr,   g_xr);
    cudaGetSymbolAddress((void**)&p_outc, g_outc);
    cudaGetSymbolAddress((void**)&p_h2,   g_h2);
    cudaGetSymbolAddress((void**)&p_t,    g_t);

    int rowBlocks = (N + 7) / 8;
    int mTiles    = (N + 127) / 128;

    init_kernel<<<(N * HEADS + 255) / 256, 256>>>(N);
    er_kernel<<<1, 32>>>(edge_emb, att_edge);
    ln_kernel<<<rowBlocks, 256>>>(x, n1w, n1b, p_h1, N);

    // relation-wise projection: x_r[r] = h1 @ weight[r]
    gemm_tf32<<<dim3(mTiles, 1, R), 256>>>(p_h1, weight, p_xr, nullptr, nullptr,
                                           N, HID, HID, 0,
                                           (long)HID * HID, (long)N * HID);
    attn_dots_kernel<<<(int)(((long)R * N + 7) / 8), 256>>>(att_src, att_dst, N, R);
    edge_pass1<<<(E + 255) / 256, 256>>>(edge_index, edge_type, E, N);
    edge_pass2<<<(E + 255) / 256, 256>>>(edge_index, E);

    // root term first (writes g_outc), then messages atomically accumulate on top
    gemm_tf32<<<dim3(mTiles, 1, 1), 256>>>(p_h1, root_w, p_outc, bias, nullptr,
                                           N, HID, HID, 0, 0, 0);
    edge_pass3<<<(E + 7) / 8, 256>>>(edge_index, edge_type, E, N);

    // elu + residual (-> d_out as x1) + LN2 (-> g_h2)
    post_kernel<<<rowBlocks, 256>>>(x, n2w, n2b, out, N);

    // FFN
    gemm_tf32<<<dim3(mTiles, 4, 1), 256>>>(p_h2, ffn_w1, p_t, ffn_b1, nullptr,
                                           N, HID, FFDIM, 1, 0, 0);
    gemm_tf32<<<dim3(mTiles, 1, 1), 256>>>(p_t, ffn_w2, out, ffn_b2, out,
                                           N, FFDIM, HID, 0, 0, 0);
}